// round 1
// baseline (speedup 1.0000x reference)
#include <cuda_runtime.h>
#include <math.h>

// Attention4DDownsample — fully fused, one CTA per batch image.
// B=2048, DIM=384, RES=7 (N=49), RES2=4 (N2=16), HEADS=8, KEY_DIM=16, D=64,
// NH_KD=128, DH=512, OUT_DIM=384.

#define THREADS 512
#define NWARP   16
#define EPS     1e-5f
#define SCALE   0.25f   // 16^-0.5

// shared memory layout (float indices)
//  xs      [0,     18816)   x[b]: 384 x 49
//  s       [18816, 24960)   q-conv input: 384 x 16   (overlapped by kv later)
//  kvs     [18816, 50176)   k_out(128x49) then v_out(512x49)
//  qo      [50176, 52224)   q_out: 128 x 16
//  bix     [52224, 53008)   bias_idxs (int), 16 x 49
//  probs   [0,     6272)    attn probs 128 x 49      (xs dead by then)
//  pre     [6272,  14464)   relu(xa + v_local): 512 x 16
#define SM_FLOATS 53008

__global__ __launch_bounds__(THREADS, 1)
void attn4dds_kernel(
    const float* __restrict__ x,
    const float* __restrict__ qlw, const float* __restrict__ qlb,
    const float* __restrict__ qpw, const float* __restrict__ qpb, const float* __restrict__ qbn,
    const float* __restrict__ kw,  const float* __restrict__ kb,  const float* __restrict__ kbn,
    const float* __restrict__ vw,  const float* __restrict__ vb,  const float* __restrict__ vbn,
    const float* __restrict__ vlw, const float* __restrict__ vlb, const float* __restrict__ vlbn,
    const float* __restrict__ pw,  const float* __restrict__ pb,  const float* __restrict__ pbn,
    const float* __restrict__ ab,  const int* __restrict__ bidx_g, int n_off,
    float* __restrict__ out)
{
    extern __shared__ float sm[];
    float* xs    = sm;
    float* s     = sm + 18816;
    float* kvs   = sm + 18816;
    float* qo    = sm + 50176;
    int*   bix   = (int*)(sm + 52224);
    float* probs = sm;
    float* pre   = sm + 6272;

    const int tid  = threadIdx.x;
    const int lane = tid & 31;
    const int wid  = tid >> 5;
    const int b    = blockIdx.x;

    // ---------- phase 1: stage x[b] and bias_idxs ----------
    {
        const float4* xin = (const float4*)(x + (size_t)b * 18816);
        float4* xs4 = (float4*)xs;
        #pragma unroll 4
        for (int i = tid; i < 4704; i += THREADS) xs4[i] = xin[i];
        for (int i = tid; i < 784; i += THREADS) bix[i] = bidx_g[i];
    }
    __syncthreads();

    // ---------- phase 2: s = local_q (dw3x3 s2 p1 + qlb) + pool_q ----------
    if (tid < 384) {
        const int c = tid;
        const float* xc = xs + c * 49;
        float w9[9];
        #pragma unroll
        for (int i = 0; i < 9; i++) w9[i] = __ldg(&qlw[c * 9 + i]);
        const float bq = __ldg(&qlb[c]);
        #pragma unroll
        for (int i = 0; i < 4; i++) {
            #pragma unroll
            for (int j = 0; j < 4; j++) {
                float acc = bq;
                #pragma unroll
                for (int ki = 0; ki < 3; ki++) {
                    const int r = 2 * i - 1 + ki;
                    if (r < 0 || r > 6) continue;
                    #pragma unroll
                    for (int kj = 0; kj < 3; kj++) {
                        const int cl = 2 * j - 1 + kj;
                        if (cl < 0 || cl > 6) continue;
                        acc += w9[ki * 3 + kj] * xc[r * 7 + cl];
                    }
                }
                float pl = 0.f;
                if (i < 3 && j < 3) {
                    pl = 0.25f * (xc[(2*i)*7 + 2*j]   + xc[(2*i)*7 + 2*j+1] +
                                  xc[(2*i+1)*7 + 2*j] + xc[(2*i+1)*7 + 2*j+1]);
                }
                s[c * 16 + i * 4 + j] = acc + pl;
            }
        }
    }
    __syncthreads();

    // ---------- phase 3: q GEMM  qo[128][16] = BN(qpw @ s + qpb) ----------
    {
        const int pos  = lane & 15;
        const int half = lane >> 4;
        for (int g = wid; g < 16; g += NWARP) {
            const int oc0 = g * 8 + half * 4;
            float acc0 = 0.f, acc1 = 0.f, acc2 = 0.f, acc3 = 0.f;
            #pragma unroll 2
            for (int c4 = 0; c4 < 96; c4++) {
                const float4 w0 = __ldg((const float4*)(qpw + (oc0 + 0) * 384 + c4 * 4));
                const float4 w1 = __ldg((const float4*)(qpw + (oc0 + 1) * 384 + c4 * 4));
                const float4 w2 = __ldg((const float4*)(qpw + (oc0 + 2) * 384 + c4 * 4));
                const float4 w3 = __ldg((const float4*)(qpw + (oc0 + 3) * 384 + c4 * 4));
                const float s0 = s[(c4 * 4 + 0) * 16 + pos];
                const float s1 = s[(c4 * 4 + 1) * 16 + pos];
                const float s2 = s[(c4 * 4 + 2) * 16 + pos];
                const float s3 = s[(c4 * 4 + 3) * 16 + pos];
                acc0 += w0.x * s0 + w0.y * s1 + w0.z * s2 + w0.w * s3;
                acc1 += w1.x * s0 + w1.y * s1 + w1.z * s2 + w1.w * s3;
                acc2 += w2.x * s0 + w2.y * s1 + w2.z * s2 + w2.w * s3;
                acc3 += w3.x * s0 + w3.y * s1 + w3.z * s2 + w3.w * s3;
            }
            float acc[4] = {acc0, acc1, acc2, acc3};
            #pragma unroll
            for (int r = 0; r < 4; r++) {
                const int oc = oc0 + r;
                const float ga = __ldg(&qbn[oc]),       be = __ldg(&qbn[128 + oc]);
                const float mn = __ldg(&qbn[256 + oc]), vr = __ldg(&qbn[384 + oc]);
                const float aa = ga * rsqrtf(vr + EPS);
                qo[oc * 16 + pos] = (acc[r] + __ldg(&qpb[oc])) * aa + (be - mn * aa);
            }
        }
    }
    __syncthreads();

    // ---------- phase 4: k/v GEMM  kvs[640][49] (overwrites s) ----------
    {
        const int p0 = lane;
        const int p1 = lane + 32;
        const bool hp1 = (lane < 17);
        for (int g = wid; g < 80; g += NWARP) {
            const int oc0 = g * 8;
            const float *Wb, *bb, *bnp; int row0, C;
            if (oc0 < 128) { Wb = kw; bb = kb; bnp = kbn; row0 = oc0;       C = 128; }
            else           { Wb = vw; bb = vb; bnp = vbn; row0 = oc0 - 128; C = 512; }
            float acc0[8], acc1[8];
            #pragma unroll
            for (int r = 0; r < 8; r++) { acc0[r] = 0.f; acc1[r] = 0.f; }
            for (int c4 = 0; c4 < 96; c4++) {
                float4 w[8];
                #pragma unroll
                for (int r = 0; r < 8; r++)
                    w[r] = __ldg((const float4*)(Wb + (row0 + r) * 384 + c4 * 4));
                const float x0a = xs[(c4*4+0)*49 + p0];
                const float x1a = xs[(c4*4+1)*49 + p0];
                const float x2a = xs[(c4*4+2)*49 + p0];
                const float x3a = xs[(c4*4+3)*49 + p0];
                const float x0b = hp1 ? xs[(c4*4+0)*49 + p1] : 0.f;
                const float x1b = hp1 ? xs[(c4*4+1)*49 + p1] : 0.f;
                const float x2b = hp1 ? xs[(c4*4+2)*49 + p1] : 0.f;
                const float x3b = hp1 ? xs[(c4*4+3)*49 + p1] : 0.f;
                #pragma unroll
                for (int r = 0; r < 8; r++) {
                    acc0[r] += w[r].x * x0a + w[r].y * x1a + w[r].z * x2a + w[r].w * x3a;
                    acc1[r] += w[r].x * x0b + w[r].y * x1b + w[r].z * x2b + w[r].w * x3b;
                }
            }
            #pragma unroll
            for (int r = 0; r < 8; r++) {
                const int oc = oc0 + r, rr = row0 + r;
                const float ga = __ldg(&bnp[rr]),         be = __ldg(&bnp[C + rr]);
                const float mn = __ldg(&bnp[2 * C + rr]), vr = __ldg(&bnp[3 * C + rr]);
                const float aa = ga * rsqrtf(vr + EPS);
                const float sh = be - mn * aa;
                const float bs = __ldg(&bb[rr]);
                kvs[oc * 49 + p0] = (acc0[r] + bs) * aa + sh;
                if (hp1) kvs[oc * 49 + p1] = (acc1[r] + bs) * aa + sh;
            }
        }
    }
    __syncthreads();

    // ---------- phase 5: attention rows (h,q), softmax over 49 ----------
    {
        for (int row = wid; row < 128; row += NWARP) {
            const int h = row >> 4, q = row & 15;
            float qv[16];
            #pragma unroll
            for (int kd = 0; kd < 16; kd++) qv[kd] = qo[(h * 16 + kd) * 16 + q];
            float a0 = 0.f, a1 = 0.f;
            #pragma unroll
            for (int kd = 0; kd < 16; kd++) {
                const float* kr = kvs + (h * 16 + kd) * 49;
                a0 += qv[kd] * kr[lane];
                if (lane < 17) a1 += qv[kd] * kr[lane + 32];
            }
            a0 = a0 * SCALE + __ldg(&ab[h * n_off + bix[q * 49 + lane]]);
            if (lane < 17) a1 = a1 * SCALE + __ldg(&ab[h * n_off + bix[q * 49 + lane + 32]]);
            else           a1 = -1e30f;
            float m = fmaxf(a0, a1);
            #pragma unroll
            for (int o = 16; o > 0; o >>= 1) m = fmaxf(m, __shfl_xor_sync(0xffffffffu, m, o));
            const float e0 = __expf(a0 - m);
            const float e1 = (lane < 17) ? __expf(a1 - m) : 0.f;
            float ss = e0 + e1;
            #pragma unroll
            for (int o = 16; o > 0; o >>= 1) ss += __shfl_xor_sync(0xffffffffu, ss, o);
            const float inv = 1.f / ss;
            probs[row * 49 + lane] = e0 * inv;
            if (lane < 17) probs[row * 49 + lane + 32] = e1 * inv;
        }
    }
    __syncthreads();

    // ---------- phase 5b: pre = relu(attn@v + v_local) , 512 x 16 ----------
    {
        const int c = tid;                 // 512 threads = 512 channels
        const float* vsm = kvs + 128 * 49 + c * 49;
        float w9[9];
        #pragma unroll
        for (int i = 0; i < 9; i++) w9[i] = __ldg(&vlw[c * 9 + i]);
        const float bl = __ldg(&vlb[c]);
        const float ga = __ldg(&vlbn[c]),          be = __ldg(&vlbn[512 + c]);
        const float mn = __ldg(&vlbn[1024 + c]),   vr = __ldg(&vlbn[1536 + c]);
        const float aa = ga * rsqrtf(vr + EPS);
        const float sh = be - mn * aa;
        const int h = c >> 6;
        #pragma unroll
        for (int i = 0; i < 4; i++) {
            #pragma unroll
            for (int j = 0; j < 4; j++) {
                float vl = bl;
                #pragma unroll
                for (int ki = 0; ki < 3; ki++) {
                    const int r = 2 * i - 1 + ki;
                    if (r < 0 || r > 6) continue;
                    #pragma unroll
                    for (int kj = 0; kj < 3; kj++) {
                        const int cl = 2 * j - 1 + kj;
                        if (cl < 0 || cl > 6) continue;
                        vl += w9[ki * 3 + kj] * vsm[r * 7 + cl];
                    }
                }
                vl = vl * aa + sh;
                const int p = i * 4 + j;
                const float* pr = probs + (h * 16 + p) * 49;
                float xa = 0.f;
                #pragma unroll
                for (int k = 0; k < 49; k++) xa += pr[k] * vsm[k];
                pre[c * 16 + p] = fmaxf(xa + vl, 0.f);
            }
        }
    }
    __syncthreads();

    // ---------- phase 6: proj GEMM  out[384][16] = BN(pw @ pre + pb) ----------
    {
        const int pos  = lane & 15;
        const int half = lane >> 4;
        float* ob = out + (size_t)b * 6144;
        for (int g = wid; g < 48; g += NWARP) {
            const int oc0 = g * 8 + half * 4;
            float acc0 = 0.f, acc1 = 0.f, acc2 = 0.f, acc3 = 0.f;
            #pragma unroll 2
            for (int c4 = 0; c4 < 128; c4++) {
                const float4 w0 = __ldg((const float4*)(pw + (oc0 + 0) * 512 + c4 * 4));
                const float4 w1 = __ldg((const float4*)(pw + (oc0 + 1) * 512 + c4 * 4));
                const float4 w2 = __ldg((const float4*)(pw + (oc0 + 2) * 512 + c4 * 4));
                const float4 w3 = __ldg((const float4*)(pw + (oc0 + 3) * 512 + c4 * 4));
                const float p0 = pre[(c4 * 4 + 0) * 16 + pos];
                const float p1 = pre[(c4 * 4 + 1) * 16 + pos];
                const float p2 = pre[(c4 * 4 + 2) * 16 + pos];
                const float p3 = pre[(c4 * 4 + 3) * 16 + pos];
                acc0 += w0.x * p0 + w0.y * p1 + w0.z * p2 + w0.w * p3;
                acc1 += w1.x * p0 + w1.y * p1 + w1.z * p2 + w1.w * p3;
                acc2 += w2.x * p0 + w2.y * p1 + w2.z * p2 + w2.w * p3;
                acc3 += w3.x * p0 + w3.y * p1 + w3.z * p2 + w3.w * p3;
            }
            float acc[4] = {acc0, acc1, acc2, acc3};
            #pragma unroll
            for (int r = 0; r < 4; r++) {
                const int oc = oc0 + r;
                const float ga = __ldg(&pbn[oc]),       be = __ldg(&pbn[384 + oc]);
                const float mn = __ldg(&pbn[768 + oc]), vr = __ldg(&pbn[1152 + oc]);
                const float aa = ga * rsqrtf(vr + EPS);
                ob[oc * 16 + pos] = (acc[r] + __ldg(&pb[oc])) * aa + (be - mn * aa);
            }
        }
    }
}

extern "C" void kernel_launch(void* const* d_in, const int* in_sizes, int n_in,
                              void* d_out, int out_size)
{
    const float* x    = (const float*)d_in[0];
    const float* qlw  = (const float*)d_in[1];
    const float* qlb  = (const float*)d_in[2];
    const float* qpw  = (const float*)d_in[3];
    const float* qpb  = (const float*)d_in[4];
    const float* qbn  = (const float*)d_in[5];
    const float* kw   = (const float*)d_in[6];
    const float* kb   = (const float*)d_in[7];
    const float* kbn  = (const float*)d_in[8];
    const float* vw   = (const float*)d_in[9];
    const float* vb   = (const float*)d_in[10];
    const float* vbn  = (const float*)d_in[11];
    const float* vlw  = (const float*)d_in[12];
    const float* vlb  = (const float*)d_in[13];
    const float* vlbn = (const float*)d_in[14];
    const float* pw   = (const float*)d_in[15];
    const float* pb   = (const float*)d_in[16];
    const float* pbn  = (const float*)d_in[17];
    const float* ab   = (const float*)d_in[18];
    const int*   bidx = (const int*)d_in[19];

    const int Bsz   = in_sizes[0] / (384 * 49);
    const int n_off = in_sizes[18] / 8;
    const size_t smem = (size_t)SM_FLOATS * sizeof(float);

    cudaFuncSetAttribute(attn4dds_kernel,
                         cudaFuncAttributeMaxDynamicSharedMemorySize, (int)smem);

    attn4dds_kernel<<<Bsz, THREADS, smem>>>(
        x, qlw, qlb, qpw, qpb, qbn, kw, kb, kbn, vw, vb, vbn,
        vlw, vlb, vlbn, pw, pb, pbn, ab, bidx, n_off, (float*)d_out);
}

// round 2
// speedup vs baseline: 1.0832x; 1.0832x over previous
#include <cuda_runtime.h>
#include <math.h>

// Attention4DDownsample — fused, one CTA per image, FFMA2 (f32x2) GEMMs.
// B=2048, DIM=384, RES=7 (N=49), RES2=4 (N2=16), HEADS=8, KEY_DIM=16, D=64,
// NH_KD=128, DH=512, OUT_DIM=384.

#define THREADS 512
#define NWARP   16
#define EPS     1e-5f
#define SCALE   0.25f

// strides (in floats)
#define XST 386   // xsT[p][c] : 49 x 384, k-contiguous, stride 386
#define SST 388   // sT[p][c]  : 16 x 384
#define KST 50    // k[oc][pos]: 128 x 49
#define VTS 513   // vT[k][c]  : 49 x 512 (odd stride -> conflict-free scatter)
#define PRS 52    // probs[row][k]: 128 x 49 (mult of 4 for float4 loads)
#define PRE 518   // preT[p][c]: 16 x 512

// shared layout (float offsets)
//  xsT  @0      : 49*386 = 18914            (dead after kv GEMM)
//  bix  @18916  : 784 ints
//  qo   @19700  : 128*16 = 2048
//  k    @21748  : 128*50 = 6400
//  vT   @28148  : 49*513 = 25137  -> end 53285
//  sT   @28148  : 16*388 = 6208   (overlays vT region; dead before kv writes)
//  probs@0      : 128*52 = 6656   (overlays xsT)
//  preT @6656   : 16*518 = 8288   -> 14944 (< 18916, bix/qo/k untouched)
#define OFF_XST   0
#define OFF_BIX   18916
#define OFF_QO    19700
#define OFF_K     21748
#define OFF_VT    28148
#define OFF_ST    28148
#define OFF_PROBS 0
#define OFF_PRE   6656
#define SM_FLOATS 53288

typedef unsigned long long ull;

__device__ __forceinline__ ull fma2(ull a, ull b, ull c) {
    ull d;
    asm("fma.rn.f32x2 %0, %1, %2, %3;" : "=l"(d) : "l"(a), "l"(b), "l"(c));
    return d;
}
__device__ __forceinline__ float psum(ull v) {
    float a, b;
    asm("mov.b64 {%0,%1}, %2;" : "=f"(a), "=f"(b) : "l"(v));
    return a + b;
}
__device__ __forceinline__ ull lds_u64(const float* p) {
    return *(const ull*)p;
}

__global__ __launch_bounds__(THREADS, 1)
void attn4dds_kernel(
    const float* __restrict__ x,
    const float* __restrict__ qlw, const float* __restrict__ qlb,
    const float* __restrict__ qpw, const float* __restrict__ qpb, const float* __restrict__ qbn,
    const float* __restrict__ kw,  const float* __restrict__ kb,  const float* __restrict__ kbn,
    const float* __restrict__ vw,  const float* __restrict__ vb,  const float* __restrict__ vbn,
    const float* __restrict__ vlw, const float* __restrict__ vlb, const float* __restrict__ vlbn,
    const float* __restrict__ pw,  const float* __restrict__ pb,  const float* __restrict__ pbn,
    const float* __restrict__ ab,  const int* __restrict__ bidx_g, int n_off,
    float* __restrict__ out)
{
    extern __shared__ float sm[];
    float* xsT   = sm + OFF_XST;
    int*   bix   = (int*)(sm + OFF_BIX);
    float* qo    = sm + OFF_QO;
    float* ksm   = sm + OFF_K;
    float* vT    = sm + OFF_VT;
    float* sT    = sm + OFF_ST;
    float* probs = sm + OFF_PROBS;
    float* preT  = sm + OFF_PRE;

    const int tid  = threadIdx.x;
    const int lane = tid & 31;
    const int wid  = tid >> 5;
    const int b    = blockIdx.x;

    // ---------- P1: stage x[b] transposed (xsT[p][c]) + bias idxs ----------
    {
        const float* xin = x + (size_t)b * 18816;
        for (int idx = tid; idx < 18816; idx += THREADS) {
            const int c = idx / 49;
            const int p = idx - c * 49;
            xsT[p * XST + c] = xin[idx];
        }
        for (int i = tid; i < 784; i += THREADS) bix[i] = bidx_g[i];
    }
    __syncthreads();

    // ---------- P2: sT[p][c] = dw3x3s2(x) + qlb + avgpool ----------
    if (tid < 384) {
        const int c = tid;
        float w9[9];
        #pragma unroll
        for (int i = 0; i < 9; i++) w9[i] = __ldg(&qlw[c * 9 + i]);
        const float bq = __ldg(&qlb[c]);
        #pragma unroll
        for (int i = 0; i < 4; i++) {
            #pragma unroll
            for (int j = 0; j < 4; j++) {
                float acc = bq;
                #pragma unroll
                for (int ki = 0; ki < 3; ki++) {
                    const int r = 2 * i - 1 + ki;
                    if (r < 0 || r > 6) continue;
                    #pragma unroll
                    for (int kj = 0; kj < 3; kj++) {
                        const int cl = 2 * j - 1 + kj;
                        if (cl < 0 || cl > 6) continue;
                        acc += w9[ki * 3 + kj] * xsT[(r * 7 + cl) * XST + c];
                    }
                }
                if (i < 3 && j < 3) {
                    acc += 0.25f * (xsT[(2*i*7 + 2*j) * XST + c]     + xsT[(2*i*7 + 2*j+1) * XST + c] +
                                    xsT[((2*i+1)*7 + 2*j) * XST + c] + xsT[((2*i+1)*7 + 2*j+1) * XST + c]);
                }
                sT[(i * 4 + j) * SST + c] = acc;
            }
        }
    }
    __syncthreads();

    // ---------- P3: q GEMM  qo[128][16] = BN(qpw @ s + qpb) ----------
    {
        const int p   = lane & 15;
        const int sub = lane >> 4;      // k-split halves
        const int oc0 = wid * 8;
        ull acc[8];
        #pragma unroll
        for (int r = 0; r < 8; r++) acc[r] = 0ULL;
        #pragma unroll 2
        for (int c8 = 0; c8 < 48; c8++) {
            const int kofs = 8 * c8 + 4 * sub;
            const ull a0 = lds_u64(&sT[p * SST + kofs]);
            const ull a1 = lds_u64(&sT[p * SST + kofs + 2]);
            #pragma unroll
            for (int r = 0; r < 8; r++) {
                const ulonglong2 w = __ldg((const ulonglong2*)(qpw + (oc0 + r) * 384 + kofs));
                acc[r] = fma2(w.x, a0, acc[r]);
                acc[r] = fma2(w.y, a1, acc[r]);
            }
        }
        #pragma unroll
        for (int r = 0; r < 8; r++) {
            float s = psum(acc[r]);
            s += __shfl_xor_sync(0xffffffffu, s, 16);
            if (sub == 0) {
                const int oc = oc0 + r;
                const float ga = __ldg(&qbn[oc]),       be = __ldg(&qbn[128 + oc]);
                const float mn = __ldg(&qbn[256 + oc]), vr = __ldg(&qbn[384 + oc]);
                const float aa = ga * rsqrtf(vr + EPS);
                qo[oc * 16 + p] = (s + __ldg(&qpb[oc])) * aa + (be - mn * aa);
            }
        }
    }
    __syncthreads();

    // ---------- P4: k/v GEMM -> ksm[128][49], vT[49][512] ----------
    {
        const int p0 = lane;
        const int p1 = lane + 32;
        const bool hp1 = (lane < 17);
        #pragma unroll 1
        for (int g = 0; g < 5; g++) {
            const int oc0 = (g * 16 + wid) * 8;
            const float *Wb, *bb, *bnp; int row0, C;
            if (oc0 < 128) { Wb = kw; bb = kb; bnp = kbn; row0 = oc0;       C = 128; }
            else           { Wb = vw; bb = vb; bnp = vbn; row0 = oc0 - 128; C = 512; }
            ull acc0[8], acc1[8];
            #pragma unroll
            for (int r = 0; r < 8; r++) { acc0[r] = 0ULL; acc1[r] = 0ULL; }
            #pragma unroll 2
            for (int c4 = 0; c4 < 96; c4++) {
                const int kofs = 4 * c4;
                const ull a00 = lds_u64(&xsT[p0 * XST + kofs]);
                const ull a01 = lds_u64(&xsT[p0 * XST + kofs + 2]);
                const ull a10 = hp1 ? lds_u64(&xsT[p1 * XST + kofs])     : 0ULL;
                const ull a11 = hp1 ? lds_u64(&xsT[p1 * XST + kofs + 2]) : 0ULL;
                #pragma unroll
                for (int r = 0; r < 8; r++) {
                    const ulonglong2 w = __ldg((const ulonglong2*)(Wb + (row0 + r) * 384 + kofs));
                    acc0[r] = fma2(w.x, a00, acc0[r]);
                    acc0[r] = fma2(w.y, a01, acc0[r]);
                    acc1[r] = fma2(w.x, a10, acc1[r]);
                    acc1[r] = fma2(w.y, a11, acc1[r]);
                }
            }
            #pragma unroll
            for (int r = 0; r < 8; r++) {
                const int oc = oc0 + r, rr = row0 + r;
                const float ga = __ldg(&bnp[rr]),         be = __ldg(&bnp[C + rr]);
                const float mn = __ldg(&bnp[2 * C + rr]), vr = __ldg(&bnp[3 * C + rr]);
                const float aa = ga * rsqrtf(vr + EPS);
                const float sh = be - mn * aa;
                const float bs = __ldg(&bb[rr]);
                const float v0 = (psum(acc0[r]) + bs) * aa + sh;
                const float v1 = (psum(acc1[r]) + bs) * aa + sh;
                if (oc < 128) {
                    ksm[oc * KST + p0] = v0;
                    if (hp1) ksm[oc * KST + p1] = v1;
                } else {
                    const int vc = oc - 128;
                    vT[p0 * VTS + vc] = v0;
                    if (hp1) vT[p1 * VTS + vc] = v1;
                }
            }
        }
    }
    __syncthreads();

    // ---------- P5: attention scores + softmax -> probs[128][49] ----------
    {
        for (int row = wid; row < 128; row += NWARP) {
            const int h = row >> 4, q = row & 15;
            float qv[16];
            #pragma unroll
            for (int kd = 0; kd < 16; kd++) qv[kd] = qo[(h * 16 + kd) * 16 + q];
            float a0 = 0.f, a1 = 0.f;
            #pragma unroll
            for (int kd = 0; kd < 16; kd++) {
                const float* kr = ksm + (h * 16 + kd) * KST;
                a0 += qv[kd] * kr[lane];
                if (lane < 17) a1 += qv[kd] * kr[lane + 32];
            }
            a0 = a0 * SCALE + __ldg(&ab[h * n_off + bix[q * 49 + lane]]);
            if (lane < 17) a1 = a1 * SCALE + __ldg(&ab[h * n_off + bix[q * 49 + lane + 32]]);
            else           a1 = -1e30f;
            float m = fmaxf(a0, a1);
            #pragma unroll
            for (int o = 16; o > 0; o >>= 1) m = fmaxf(m, __shfl_xor_sync(0xffffffffu, m, o));
            const float e0 = __expf(a0 - m);
            const float e1 = (lane < 17) ? __expf(a1 - m) : 0.f;
            float ss = e0 + e1;
            #pragma unroll
            for (int o = 16; o > 0; o >>= 1) ss += __shfl_xor_sync(0xffffffffu, ss, o);
            const float inv = 1.f / ss;
            probs[row * PRS + lane] = e0 * inv;
            if (lane < 17) probs[row * PRS + lane + 32] = e1 * inv;
        }
    }
    __syncthreads();

    // ---------- P5b: preT[p][c] = relu(attn@v + BN(v_local)) ----------
    {
        const int c = tid;          // 512 threads = 512 channels
        const int h = c >> 6;
        float acc[16];
        #pragma unroll
        for (int p = 0; p < 16; p++) acc[p] = 0.f;
        // dot: k = 0..47 via float4 broadcast probs + register v
        #pragma unroll 2
        for (int k4 = 0; k4 < 12; k4++) {
            const float v0 = vT[(4 * k4 + 0) * VTS + c];
            const float v1 = vT[(4 * k4 + 1) * VTS + c];
            const float v2 = vT[(4 * k4 + 2) * VTS + c];
            const float v3 = vT[(4 * k4 + 3) * VTS + c];
            #pragma unroll
            for (int p = 0; p < 16; p++) {
                const float4 pr = *(const float4*)&probs[(h * 16 + p) * PRS + 4 * k4];
                acc[p] += pr.x * v0 + pr.y * v1 + pr.z * v2 + pr.w * v3;
            }
        }
        {   // k = 48 tail
            const float v48 = vT[48 * VTS + c];
            #pragma unroll
            for (int p = 0; p < 16; p++)
                acc[p] += probs[(h * 16 + p) * PRS + 48] * v48;
        }
        // depthwise conv on v + BN, add, relu, store
        float w9[9];
        #pragma unroll
        for (int i = 0; i < 9; i++) w9[i] = __ldg(&vlw[c * 9 + i]);
        const float bl = __ldg(&vlb[c]);
        const float ga = __ldg(&vlbn[c]),        be = __ldg(&vlbn[512 + c]);
        const float mn = __ldg(&vlbn[1024 + c]), vr = __ldg(&vlbn[1536 + c]);
        const float aa = ga * rsqrtf(vr + EPS);
        const float sh = be - mn * aa;
        #pragma unroll
        for (int i = 0; i < 4; i++) {
            #pragma unroll
            for (int j = 0; j < 4; j++) {
                float vl = bl;
                #pragma unroll
                for (int ki = 0; ki < 3; ki++) {
                    const int r = 2 * i - 1 + ki;
                    if (r < 0 || r > 6) continue;
                    #pragma unroll
                    for (int kj = 0; kj < 3; kj++) {
                        const int cl = 2 * j - 1 + kj;
                        if (cl < 0 || cl > 6) continue;
                        vl += w9[ki * 3 + kj] * vT[(r * 7 + cl) * VTS + c];
                    }
                }
                const int p = i * 4 + j;
                preT[p * PRE + c] = fmaxf(acc[p] + vl * aa + sh, 0.f);
            }
        }
    }
    __syncthreads();

    // ---------- P6: proj GEMM  out[384][16] = BN(pw @ pre + pb) ----------
    {
        const int p   = lane & 15;
        const int sub = lane >> 4;
        float* ob = out + (size_t)b * 6144;
        #pragma unroll 1
        for (int g = 0; g < 3; g++) {
            const int oc0 = (g * 16 + wid) * 8;
            ull acc[8];
            #pragma unroll
            for (int r = 0; r < 8; r++) acc[r] = 0ULL;
            #pragma unroll 2
            for (int c8 = 0; c8 < 64; c8++) {
                const int kofs = 8 * c8 + 4 * sub;
                const ull a0 = lds_u64(&preT[p * PRE + kofs]);
                const ull a1 = lds_u64(&preT[p * PRE + kofs + 2]);
                #pragma unroll
                for (int r = 0; r < 8; r++) {
                    const ulonglong2 w = __ldg((const ulonglong2*)(pw + (oc0 + r) * 512 + kofs));
                    acc[r] = fma2(w.x, a0, acc[r]);
                    acc[r] = fma2(w.y, a1, acc[r]);
                }
            }
            #pragma unroll
            for (int r = 0; r < 8; r++) {
                float s = psum(acc[r]);
                s += __shfl_xor_sync(0xffffffffu, s, 16);
                if (sub == 0) {
                    const int oc = oc0 + r;
                    const float ga = __ldg(&pbn[oc]),       be = __ldg(&pbn[384 + oc]);
                    const float mn = __ldg(&pbn[768 + oc]), vr = __ldg(&pbn[1152 + oc]);
                    const float aa = ga * rsqrtf(vr + EPS);
                    ob[oc * 16 + p] = (s + __ldg(&pb[oc])) * aa + (be - mn * aa);
                }
            }
        }
    }
}

extern "C" void kernel_launch(void* const* d_in, const int* in_sizes, int n_in,
                              void* d_out, int out_size)
{
    const float* x    = (const float*)d_in[0];
    const float* qlw  = (const float*)d_in[1];
    const float* qlb  = (const float*)d_in[2];
    const float* qpw  = (const float*)d_in[3];
    const float* qpb  = (const float*)d_in[4];
    const float* qbn  = (const float*)d_in[5];
    const float* kw   = (const float*)d_in[6];
    const float* kb   = (const float*)d_in[7];
    const float* kbn  = (const float*)d_in[8];
    const float* vw   = (const float*)d_in[9];
    const float* vb   = (const float*)d_in[10];
    const float* vbn  = (const float*)d_in[11];
    const float* vlw  = (const float*)d_in[12];
    const float* vlb  = (const float*)d_in[13];
    const float* vlbn = (const float*)d_in[14];
    const float* pw   = (const float*)d_in[15];
    const float* pb   = (const float*)d_in[16];
    const float* pbn  = (const float*)d_in[17];
    const float* ab   = (const float*)d_in[18];
    const int*   bidx = (const int*)d_in[19];

    const int Bsz   = in_sizes[0] / (384 * 49);
    const int n_off = in_sizes[18] / 8;
    const size_t smem = (size_t)SM_FLOATS * sizeof(float);

    cudaFuncSetAttribute(attn4dds_kernel,
                         cudaFuncAttributeMaxDynamicSharedMemorySize, (int)smem);

    attn4dds_kernel<<<Bsz, THREADS, smem>>>(
        x, qlw, qlb, qpw, qpb, qbn, kw, kb, kbn, vw, vb, vbn,
        vlw, vlb, vlbn, pw, pb, pbn, ab, bidx, n_off, (float*)d_out);
}